// round 2
// baseline (speedup 1.0000x reference)
#include <cuda_runtime.h>

// DynamicMaskHead fused kernel for GB300 (sm_103a), round 2.
// - Packed f32x2 FFMA for the per-instance MLP (2 pixels per instruction).
// - Block-uniform weights pre-duplicated in smem as {w,w} pairs -> LDS.64 gives
//   a packed operand directly (broadcast, conflict-free).
// - Grid split into 3 row-slabs per (inst, head): smem 22.5KB, 1200 blocks,
//   ~4 full waves at occ 2 (kills the 1.35-wave tail of round 1).

#define HH       96
#define WW       160
#define HW       15360
#define OWw      320
#define NP       169
#define NTHREADS 256
#define SLAB     32          // input rows per block (plus 1 overlap row if not first)

typedef unsigned long long u64;

__device__ __forceinline__ u64 pk(float lo, float hi) {
    u64 r; asm("mov.b64 %0, {%1, %2};" : "=l"(r) : "f"(lo), "f"(hi)); return r;
}
__device__ __forceinline__ void upk(u64 v, float& lo, float& hi) {
    asm("mov.b64 {%0, %1}, %2;" : "=f"(lo), "=f"(hi) : "l"(v));
}
__device__ __forceinline__ u64 ffma2(u64 a, u64 b, u64 c) {
    u64 d; asm("fma.rn.f32x2 %0, %1, %2, %3;" : "=l"(d) : "l"(a), "l"(b), "l"(c)); return d;
}
__device__ __forceinline__ u64 relu2(u64 v) {
    float lo, hi; upk(v, lo, hi);
    return pk(fmaxf(lo, 0.0f), fmaxf(hi, 0.0f));
}

__global__ __launch_bounds__(NTHREADS, 2)
void dmh_kernel(const float* __restrict__ feats,     // [2, 8, 96, 160]
                const float* __restrict__ p1,        // [N, 169]
                const float* __restrict__ p2,        // [N, 169]
                const float* __restrict__ loc,       // [N, 2]
                const float* __restrict__ off,       // [N, 2]
                const int*   __restrict__ imi,       // [N]
                const int*   __restrict__ fpn,       // [N]
                float*       __restrict__ out)       // [2, N, 192, 320]
{
    __shared__ float sL[(SLAB + 1) * WW];   // logits slab (33 rows max)
    __shared__ u64   spk[NP];               // params duplicated {w,w}

    const int tid    = threadIdx.x;
    const int inst   = blockIdx.x;
    const int head   = blockIdx.y;
    const int slab   = blockIdx.z;          // 0..2
    const int n_inst = gridDim.x;

    const float* params = (head == 0 ? p1 : p2) + inst * NP;
    if (tid < NP) {
        const float w = params[tid];
        spk[tid] = pk(w, w);
    }

    const int   lvl     = fpn[inst];
    const float inv_soi = 1.0f / (64.0f * (float)(1 << lvl));
    float lx = loc[2 * inst + 0];
    float ly = loc[2 * inst + 1];
    if (head) {
        lx += off[2 * inst + 0] * 128.0f;
        ly += off[2 * inst + 1] * 128.0f;
    }
    const float* fb = feats + (size_t)imi[inst] * (8 * HW);
    __syncthreads();

    // ---------------- Phase 1: MLP over slab rows (4 px/thread/iter) ---------
    const int ybase = (slab == 0) ? 0 : (SLAB * slab - 1);   // first smem row
    const int nrows = SLAB + (slab != 0);                    // 32 or 33
    const int nq    = nrows * (WW / 4);                      // quads in slab
    const float dx  = -8.0f * inv_soi;

    #pragma unroll 1
    for (int q = tid; q < nq; q += NTHREADS) {
        const int row = q / (WW / 4);
        const int px0 = (q - row * (WW / 4)) * 4;
        const int y   = ybase + row;

        u64 x01[10], x23[10];
        {
            const float cy  = (ly - (float)(y * 8 + 4)) * inv_soi;
            const float cx0 = (lx - (float)(px0 * 8 + 4)) * inv_soi;
            x01[0] = pk(cx0, cx0 + dx);
            x23[0] = pk(cx0 + 2.0f * dx, cx0 + 3.0f * dx);
            x01[1] = pk(cy, cy);
            x23[1] = x01[1];
        }
        const int base = y * WW + px0;
        #pragma unroll
        for (int c = 0; c < 8; ++c) {
            const float4 v = *reinterpret_cast<const float4*>(fb + c * HW + base);
            x01[2 + c] = pk(v.x, v.y);
            x23[2 + c] = pk(v.z, v.w);
        }

        // Layer 0: [8 x 10] + bias, ReLU
        u64 h01[8], h23[8];
        #pragma unroll
        for (int c = 0; c < 8; ++c) {
            const u64 b = spk[152 + c];
            u64 a01 = b, a23 = b;
            #pragma unroll
            for (int i = 0; i < 10; ++i) {
                const u64 w = spk[c * 10 + i];
                a01 = ffma2(x01[i], w, a01);
                a23 = ffma2(x23[i], w, a23);
            }
            h01[c] = relu2(a01);
            h23[c] = relu2(a23);
        }

        // Layer 1: [8 x 8] + bias, ReLU
        u64 g01[8], g23[8];
        #pragma unroll
        for (int c = 0; c < 8; ++c) {
            const u64 b = spk[160 + c];
            u64 a01 = b, a23 = b;
            #pragma unroll
            for (int i = 0; i < 8; ++i) {
                const u64 w = spk[80 + c * 8 + i];
                a01 = ffma2(h01[i], w, a01);
                a23 = ffma2(h23[i], w, a23);
            }
            g01[c] = relu2(a01);
            g23[c] = relu2(a23);
        }

        // Layer 2: [1 x 8] + bias
        const u64 b2 = spk[168];
        u64 o01 = b2, o23 = b2;
        #pragma unroll
        for (int c = 0; c < 8; ++c) {
            const u64 w = spk[144 + c];
            o01 = ffma2(g01[c], w, o01);
            o23 = ffma2(g23[c], w, o23);
        }
        float o0, o1, o2, o3;
        upk(o01, o0, o1);
        upk(o23, o2, o3);
        *reinterpret_cast<float4*>(sL + row * WW + px0) = make_float4(o0, o1, o2, o3);
    }
    __syncthreads();

    // ---------------- Phase 2: aligned_bilinear x2 + sigmoid -----------------
    // Per axis (factor 2): out[0]=t[0]; out[2k+1]=t[k]; out[2k]=0.5*(t[k-1]+t[k])
    float* ob = out + ((size_t)head * n_inst + inst) * (size_t)(2 * HH * OWw)
              + (size_t)(2 * SLAB * slab) * OWw;

    #pragma unroll 1
    for (int it = 0; it < (2 * SLAB * OWw) / (NTHREADS * 4); ++it) {   // 20 iters
        const int q    = tid + it * NTHREADS;
        const int oyl  = q / (OWw / 4);                 // 0..63 local output row
        const int ox4  = (q - oyl * (OWw / 4)) * 4;
        const int oy   = 2 * SLAB * slab + oyl;         // global output row
        const int c    = ox4 >> 1;
        const int cm1  = (c > 0) ? c - 1 : 0;

        int r0, r1; float w0, w1;
        if (oy & 1)       { r0 = (oy >> 1) - ybase; r1 = r0;     w0 = 1.0f; w1 = 0.0f; }
        else if (oy == 0) { r0 = 0;                 r1 = 0;      w0 = 1.0f; w1 = 0.0f; }
        else              { r1 = (oy >> 1) - ybase; r0 = r1 - 1; w0 = 0.5f; w1 = 0.5f; }

        const float* row0 = sL + r0 * WW;
        const float* row1 = sL + r1 * WW;
        const float A = w0 * row0[cm1]   + w1 * row1[cm1];
        const float B = w0 * row0[c]     + w1 * row1[c];
        const float C = w0 * row0[c + 1] + w1 * row1[c + 1];

        float4 v;
        v.x = (ox4 == 0) ? B : 0.5f * (A + B);
        v.y = B;
        v.z = 0.5f * (B + C);
        v.w = C;

        v.x = 1.0f / (1.0f + __expf(-v.x));
        v.y = 1.0f / (1.0f + __expf(-v.y));
        v.z = 1.0f / (1.0f + __expf(-v.z));
        v.w = 1.0f / (1.0f + __expf(-v.w));

        *reinterpret_cast<float4*>(ob + oyl * OWw + ox4) = v;
    }
}

extern "C" void kernel_launch(void* const* d_in, const int* in_sizes, int n_in,
                              void* d_out, int out_size)
{
    const float* feats = (const float*)d_in[0];
    const float* p1    = (const float*)d_in[1];
    const float* p2    = (const float*)d_in[2];
    const float* loc   = (const float*)d_in[3];
    const float* off   = (const float*)d_in[4];
    const int*   imi   = (const int*)  d_in[5];
    const int*   fpn   = (const int*)  d_in[6];
    float* out = (float*)d_out;

    const int n_inst = in_sizes[5];   // 200

    dim3 grid(n_inst, 2, HH / SLAB);  // (200, 2, 3) = 1200 blocks
    dmh_kernel<<<grid, NTHREADS>>>(feats, p1, p2, loc, off, imi, fpn, out);
}